// round 9
// baseline (speedup 1.0000x reference)
#include <cuda_runtime.h>
#include <cstdint>

// Verblizer: per-token argmax(20) -> expert Linear(2,2) -> softmax(2) -> y,
// plus permuted copy y2 (pu rows first, then non-pu rows in order).
// d_out[0..2S) = y, d_out[2S..4S) = y2.
//
// SINGLE kernel. Each block finds its pu window bounds with two concurrent
// warp-ballot lower_bounds (4 parallel-gather rounds each), overlapped with
// the tile-0 cp.async staging. Body is the proven R4/R8 streaming loop with
// inline per-tile y2 writes (no tail deferral).

#define THREADS 256
#define TILE    256
#define NTILES  4
#define CHUNK   (TILE * NTILES)      // 1024 tokens per block

__device__ __forceinline__ void cp_async16(uint32_t smem_dst, const void* gptr) {
    asm volatile("cp.async.cg.shared.global [%0], [%1], 16;\n" :: "r"(smem_dst), "l"(gptr));
}
__device__ __forceinline__ void cp_commit() { asm volatile("cp.async.commit_group;\n"); }
template<int N> __device__ __forceinline__ void cp_wait() {
    asm volatile("cp.async.wait_group %0;\n" :: "n"(N));
}

// warp-cooperative lower_bound over sorted pu[0..P): 32-way narrowing,
// ~4 parallel-gather rounds. Invariant: answer in [lo, hi] inclusive.
__device__ __forceinline__ int warp_lower_bound(const int* __restrict__ pu, int P, int target)
{
    const int lane = threadIdx.x & 31;
    int lo = 0, hi = P;
    while (hi - lo > 32) {
        const int step = (hi - lo + 31) >> 5;
        const int p = lo + lane * step;
        const int v = (p < hi) ? __ldg(pu + p) : 0x7fffffff;
        const unsigned mask = __ballot_sync(0xffffffffu, v < target);
        if (mask == 0) return lo;              // pu[lo] >= target -> lb == lo
        const int lstar = 31 - __clz(mask);
        const int nl = lo + lstar * step;      // pu[nl] < target
        hi = min(hi, nl + step);               // answer <= nl + step
        lo = nl + 1;
    }
    const int p = lo + lane;
    const int v = (p < hi) ? __ldg(pu + p) : 0x7fffffff;
    const unsigned mask = __ballot_sync(0xffffffffu, v < target);
    return lo + __popc(mask);                  // contiguous mask (sorted input)
}

__global__ __launch_bounds__(THREADS)
void verblizer_kernel(const float*  __restrict__ x,
                      const float*  __restrict__ h,
                      const float*  __restrict__ W,
                      const float*  __restrict__ b,
                      const int*    __restrict__ pu,
                      int S, int P,
                      float* __restrict__ out)
{
    __shared__ float4 sx[2][TILE * 5];   // 2 x 20KB staged x tiles
    __shared__ int    spu[CHUNK];        // 4KB pu window
    __shared__ float4 sW[20];
    __shared__ float2 sB[20];
    __shared__ int    s_lb[2];           // [lb0, lb_end]

    const int tid = threadIdx.x;
    const int bs  = blockIdx.x * CHUNK;

    if (tid < 20) {
        sW[tid] = reinterpret_cast<const float4*>(W)[tid];
        sB[tid] = reinterpret_cast<const float2*>(b)[tid];
    }

    const char* __restrict__ xb = reinterpret_cast<const char*>(x);
    const float2* __restrict__ h2 = reinterpret_cast<const float2*>(h);
    float2* __restrict__ outy  = reinterpret_cast<float2*>(out);
    float2* __restrict__ outy2 = reinterpret_cast<float2*>(out + (size_t)2 * S);

    // ---- issue tile-0 staging first; searches overlap its DRAM latency ----
    {
        const int vt  = min(TILE, S - bs);
        const int vt5 = vt * 5;
        uint32_t dst = (uint32_t)__cvta_generic_to_shared(&sx[0][0]);
        #pragma unroll
        for (int r = 0; r < 5; r++) {
            const int c = tid + r * THREADS;
            if (c < vt5) cp_async16(dst + c * 16, xb + (size_t)bs * 80 + (size_t)c * 16);
        }
        cp_commit();
    }

    // ---- two concurrent warp-ballot lower_bounds (warp 0: bs, warp 1: bs+CHUNK) ----
    const int wid = tid >> 5;
    if (wid < 2) {
        const int lb = warp_lower_bound(pu, P, bs + wid * CHUNK);
        if ((tid & 31) == 0) s_lb[wid] = lb;
    }
    __syncthreads();

    const int lb0 = s_lb[0];
    const int n   = s_lb[1] - lb0;       // pu entries in window (<= CHUNK)

    // stage pu window (coalesced; visible after first in-loop __syncthreads)
    for (int i = tid; i < n; i += THREADS) spu[i] = __ldg(pu + lb0 + i);

    #pragma unroll
    for (int t = 0; t < NTILES; t++) {
        if (t + 1 < NTILES) {
            const int tb  = bs + (t + 1) * TILE;
            const int vt  = min(TILE, S - tb);
            const int vt5 = vt * 5;
            uint32_t dst = (uint32_t)__cvta_generic_to_shared(&sx[(t + 1) & 1][0]);
            #pragma unroll
            for (int r = 0; r < 5; r++) {
                const int c = tid + r * THREADS;
                if (c < vt5) cp_async16(dst + c * 16, xb + (size_t)tb * 80 + (size_t)c * 16);
            }
            cp_commit();
            cp_wait<1>();
        } else {
            cp_wait<0>();
        }
        __syncthreads();

        const int s = bs + t * TILE + tid;
        if (s < S) {
            const float4* __restrict__ row = &sx[t & 1][tid * 5];

            // ---- exact argmax over 20 f32 (first-index tie-break) ----
            const float4 q0 = row[0], q1 = row[1], q2 = row[2], q3 = row[3], q4 = row[4];
            const float g0 = fmaxf(fmaxf(q0.x, q0.y), fmaxf(q0.z, q0.w));
            const float g1 = fmaxf(fmaxf(q1.x, q1.y), fmaxf(q1.z, q1.w));
            const float g2 = fmaxf(fmaxf(q2.x, q2.y), fmaxf(q2.z, q2.w));
            const float g3 = fmaxf(fmaxf(q3.x, q3.y), fmaxf(q3.z, q3.w));
            const float g4 = fmaxf(fmaxf(q4.x, q4.y), fmaxf(q4.z, q4.w));
            const float M  = fmaxf(g4, fmaxf(fmaxf(g0, g1), fmaxf(g2, g3)));

            int gi = 4;
            gi = (g3 == M) ? 3 : gi;
            gi = (g2 == M) ? 2 : gi;
            gi = (g1 == M) ? 1 : gi;
            gi = (g0 == M) ? 0 : gi;

            const float4 qw = row[gi];           // LDS reload of winning quad
            int li = 3;
            li = (qw.z == M) ? 2 : li;
            li = (qw.y == M) ? 1 : li;
            li = (qw.x == M) ? 0 : li;
            const int e = gi * 4 + li;

            // ---- expert Linear(2,2) + softmax(2) ----
            const float2 hv = h2[s];
            const float4 w  = sW[e];
            const float2 bb = sB[e];
            const float y0 = fmaf(hv.x, w.x, fmaf(hv.y, w.y, bb.x));
            const float y1 = fmaf(hv.x, w.z, fmaf(hv.y, w.w, bb.y));
            const float ed  = __expf(y1 - y0);
            const float inv = __fdividef(1.0f, 1.0f + ed);
            float2 yo;
            yo.x = inv;
            yo.y = ed * inv;

            outy[s] = yo;

            // ---- permutation destination: lb = lb0 + lower_bound(spu, s) ----
            int lo = 0, hi = n;
            while (lo < hi) {
                int mid = (lo + hi) >> 1;
                if (spu[mid] < s) lo = mid + 1; else hi = mid;
            }
            const int  cur  = (lo < n) ? spu[lo] : 0x7fffffff;
            const bool ispu = (cur == s);
            const int  dest = ispu ? (lb0 + lo) : (P + s - lb0 - lo);
            outy2[dest] = yo;
        }
        __syncthreads();
    }
}

extern "C" void kernel_launch(void* const* d_in, const int* in_sizes, int n_in,
                              void* d_out, int out_size)
{
    const float* x  = (const float*)d_in[0];   // [1, S, 20]
    const float* h  = (const float*)d_in[1];   // [S, 2]
    const float* W  = (const float*)d_in[2];   // [20, 2, 2]
    const float* b  = (const float*)d_in[3];   // [20, 2]
    const int*   pu = (const int*)  d_in[4];   // [P]

    const int S = in_sizes[1] / 2;
    const int P = in_sizes[4];
    const int blocks = (S + CHUNK - 1) / CHUNK;

    verblizer_kernel<<<blocks, THREADS>>>(x, h, W, b, pu, S, P, (float*)d_out);
}